// round 14
// baseline (speedup 1.0000x reference)
#include <cuda_runtime.h>

// TwistJMotorInt8: 4 rounds of {row-max quantize to +-42 ints, integer MJ
// butterfly on groups of 4 (rolled by 2 on Thue-Morse odd steps), dequantize},
// then out = x*scale + bias.  One CTA per 4096-float row.
//
// Reference-arithmetic model (composed XLA algsimp rewrites, uniform rounds):
//   (1) div-by-const:        qs = RN(max * RN(1/42))
//   (2) div-by-broadcast ->  r  = div.rn(1, qs);  q = roundeven(RN(x * r))
//   dequant multiplies by qs; epilogue separate RN mul/add.
// The quantized lattice is tie-dense from round 1 on, so both scale legs and
// the elementwise op flavor are semantic at the 1-ulp level.

#define DIM     4096
#define THREADS 256

// Padded smem index: +1 float every 32 to break stride-16 bank conflicts.
__device__ __forceinline__ int phys(int i) { return i + (i >> 5); }

__global__ void __launch_bounds__(THREADS)
twist_kernel(const float* __restrict__ x,
             const float* __restrict__ scale,
             const float* __restrict__ bias,
             float* __restrict__ out)
{
    __shared__ float s_red[8];
    __shared__ float s_max;
    __shared__ float s_q[DIM + DIM / 32];   // padded quantized row

    const int t    = threadIdx.x;
    const int lane = t & 31;
    const int wid  = t >> 5;
    const long long rowbase = (long long)blockIdx.x * DIM;

    // Coalesced load: elements 16t .. 16t+15.
    float v[16];
    const float4* __restrict__ xin = (const float4*)(x + rowbase) + t * 4;
    #pragma unroll
    for (int c = 0; c < 4; c++) {
        float4 w = xin[c];
        v[4*c+0] = w.x; v[4*c+1] = w.y; v[4*c+2] = w.z; v[4*c+3] = w.w;
    }

    const float inv42 = 1.0f / 42.0f;   // RN(1/42), compile-time constant

    #pragma unroll
    for (int step = 0; step < 4; step++) {
        // ---------- row max of |v| ----------
        float m = 0.0f;
        #pragma unroll
        for (int i = 0; i < 16; i++) m = fmaxf(m, fabsf(v[i]));
        #pragma unroll
        for (int o = 16; o; o >>= 1)
            m = fmaxf(m, __shfl_xor_sync(0xffffffffu, m, o));
        if (lane == 0) s_red[wid] = m;
        __syncthreads();
        if (t == 0) {
            float mm = s_red[0];
            #pragma unroll
            for (int i = 1; i < 8; i++) mm = fmaxf(mm, s_red[i]);
            s_max = mm;
        }
        __syncthreads();

        const float maxv = fmaxf(s_max, 1e-12f);
        const float qs   = __fmul_rn(maxv, inv42);   // qs flavor B
        const float r    = __fdiv_rn(1.0f, qs);      // hoisted RN reciprocal

        // ---------- quantize: roundeven(RN(x * r)), clip [-42, 42] ----------
        float q[16];
        #pragma unroll
        for (int i = 0; i < 16; i++) {
            float d = rintf(__fmul_rn(v[i], r));
            q[i] = fminf(fmaxf(d, -42.0f), 42.0f);
        }

        const bool roll = (step == 1) || (step == 2);   // Thue-Morse 0,1,1,0

        if (roll) {
            // Stage the full quantized row in shared memory.
            #pragma unroll
            for (int i = 0; i < 16; i++) s_q[phys(16 * t + i)] = q[i];
            __syncthreads();

            // Composite of roll(+2) -> MJ -> roll(-2), per 4-group:
            //   y[b+0] = q[b-2]
            //   y[b+1] = q[b-1] - q[b]   + q[b+1]
            //   y[b+2] = q[b+2] - q[b+4] + q[b+5]
            //   y[b+3] = q[b+3] - q[b+4]      (indices mod DIM)
            #pragma unroll
            for (int k = 0; k < 4; k++) {
                const int b = 16 * t + 4 * k;
                const float am2 = s_q[phys((b - 2 + DIM) & (DIM - 1))];
                const float am1 = s_q[phys((b - 1 + DIM) & (DIM - 1))];
                const float b4  = s_q[phys((b + 4)       & (DIM - 1))];
                const float b5  = s_q[phys((b + 5)       & (DIM - 1))];
                const float x0 = q[4*k+0], x1 = q[4*k+1];
                const float x2 = q[4*k+2], x3 = q[4*k+3];
                v[4*k+0] = am2;
                v[4*k+1] = am1 - x0 + x1;
                v[4*k+2] = x2 - b4 + b5;
                v[4*k+3] = x3 - b4;
            }
            // Reads above complete before the next step's s_q writes, which
            // sit behind that step's two reduction __syncthreads.
        } else {
            // MJ in registers: y = [x0-x2+x3, x1-x2, x0, x1-x2+x3]
            #pragma unroll
            for (int k = 0; k < 4; k++) {
                const float x0 = q[4*k+0], x1 = q[4*k+1];
                const float x2 = q[4*k+2], x3 = q[4*k+3];
                const float y1 = x1 - x2;
                v[4*k+0] = x0 - x2 + x3;
                v[4*k+1] = y1;
                v[4*k+2] = x0;
                v[4*k+3] = y1 + x3;
            }
        }

        // ---------- dequantize (exact RN multiply, integer * qs) ----------
        #pragma unroll
        for (int i = 0; i < 16; i++) v[i] = __fmul_rn(v[i], qs);
    }

    // ---------- epilogue: out = v*scale + bias (separate RN mul, RN add) ----
    float4* __restrict__ o4 = (float4*)(out + rowbase) + t * 4;
    const float4* __restrict__ sc4 = (const float4*)scale + t * 4;
    const float4* __restrict__ bi4 = (const float4*)bias  + t * 4;
    #pragma unroll
    for (int c = 0; c < 4; c++) {
        const float4 s = __ldg(sc4 + c);
        const float4 b = __ldg(bi4 + c);
        float4 r;
        r.x = __fadd_rn(__fmul_rn(v[4*c+0], s.x), b.x);
        r.y = __fadd_rn(__fmul_rn(v[4*c+1], s.y), b.y);
        r.z = __fadd_rn(__fmul_rn(v[4*c+2], s.z), b.z);
        r.w = __fadd_rn(__fmul_rn(v[4*c+3], s.w), b.w);
        o4[c] = r;
    }
}

extern "C" void kernel_launch(void* const* d_in, const int* in_sizes, int n_in,
                              void* d_out, int out_size) {
    const float* x     = (const float*)d_in[0];
    const float* scale = (const float*)d_in[1];
    const float* bias  = (const float*)d_in[2];
    float* out         = (float*)d_out;
    const int rows = in_sizes[0] / DIM;   // 16384
    twist_kernel<<<rows, THREADS>>>(x, scale, bias, out);
}

// round 15
// speedup vs baseline: 1.2532x; 1.2532x over previous
#include <cuda_runtime.h>
#include <cstdint>

// TwistJMotorInt8: 4 rounds of {row-max quantize to +-42 ints, integer MJ
// butterfly on groups of 4 (rolled by 2 on Thue-Morse odd steps), dequantize},
// then out = x*scale + bias.  One CTA per 4096-float row.
//
// Verified bit-exact numerics (rel_err == 0.0 in R14) — DO NOT CHANGE:
//   qs = RN(max * RN(1/42));  r = div.rn(1, qs)
//   q  = clip(roundeven(RN(x * r)), -42, 42)
//   dequant = RN(y * qs); epilogue = separate RN mul / RN add.
//
// Perf changes vs R14 (numerics-neutral):
//   - roll halo: stage only 2 boundary float2 per thread; recompute neighbor
//     q locally with the identical quantize op (same r => same bits)
//   - warp max via redux.sync on |v| bit patterns; 8 partials read as uint4
//   - 1 __syncthreads per step (reduction + halo share the barrier),
//     double-buffered smem by step parity

#define DIM     4096
#define THREADS 256

__device__ __forceinline__ float clipq(float x, float r) {
    float d = rintf(__fmul_rn(x, r));
    return fminf(fmaxf(d, -42.0f), 42.0f);
}

__global__ void __launch_bounds__(THREADS)
twist_kernel(const float* __restrict__ x,
             const float* __restrict__ scale,
             const float* __restrict__ bias,
             float* __restrict__ out)
{
    __shared__ __align__(16) unsigned s_red[2][8];  // per-parity max partials
    __shared__ float2 sA[2][THREADS];               // (v[0], v[1])  per roll step
    __shared__ float2 sB[2][THREADS];               // (v[14],v[15]) per roll step

    const int t    = threadIdx.x;
    const int lane = t & 31;
    const int wid  = t >> 5;
    const long long rowbase = (long long)blockIdx.x * DIM;

    // Coalesced load: elements 16t .. 16t+15.
    float v[16];
    const float4* __restrict__ xin = (const float4*)(x + rowbase) + t * 4;
    #pragma unroll
    for (int c = 0; c < 4; c++) {
        float4 w = xin[c];
        v[4*c+0] = w.x; v[4*c+1] = w.y; v[4*c+2] = w.z; v[4*c+3] = w.w;
    }

    const float inv42 = 1.0f / 42.0f;   // RN(1/42)

    #pragma unroll
    for (int step = 0; step < 4; step++) {
        const int  p    = step & 1;
        const bool roll = (step == 1) || (step == 2);   // Thue-Morse 0,1,1,0
        const int  rb   = step - 1;                     // halo buffer (1->0, 2->1)

        // ---- warp-level max of |v| (bit-monotonic for non-negative f32) ----
        float m = fabsf(v[0]);
        #pragma unroll
        for (int i = 1; i < 16; i++) m = fmaxf(m, fabsf(v[i]));
        unsigned um = __reduce_max_sync(0xffffffffu, __float_as_uint(m));
        if (lane == 0) s_red[p][wid] = um;

        // ---- stage 2-element halo pairs (roll steps only) ----
        if (roll) {
            sA[rb][t] = make_float2(v[0],  v[1]);
            sB[rb][t] = make_float2(v[14], v[15]);
        }
        __syncthreads();   // serves both the reduction and the halo exchange

        // ---- finish max across 8 warps (two uint4 broadcasts) ----
        const uint4* sr = (const uint4*)s_red[p];
        uint4 a = sr[0], b = sr[1];
        unsigned mm = max(max(max(a.x, a.y), max(a.z, a.w)),
                          max(max(b.x, b.y), max(b.z, b.w)));
        const float maxv = fmaxf(__uint_as_float(mm), 1e-12f);
        const float qs   = __fmul_rn(maxv, inv42);   // dequant scale
        const float r    = __fdiv_rn(1.0f, qs);      // hoisted RN reciprocal

        if (roll) {
            // Neighbor halo (ring of 256 threads == one 4096 row).
            const float2 L = sB[rb][(t + THREADS - 1) & (THREADS - 1)];
            const float2 R = sA[rb][(t + 1) & (THREADS - 1)];

            // Extended quantized window qe[0..19] = q[16t-2 .. 16t+17].
            float qe[20];
            qe[0] = clipq(L.x, r);  qe[1] = clipq(L.y, r);
            #pragma unroll
            for (int i = 0; i < 16; i++) qe[2 + i] = clipq(v[i], r);
            qe[18] = clipq(R.x, r); qe[19] = clipq(R.y, r);

            // Composite roll(+2) -> MJ -> roll(-2) per 4-group:
            //   y[g+0] = q[g-2]
            //   y[g+1] = q[g-1] - q[g]   + q[g+1]
            //   y[g+2] = q[g+2] - q[g+4] + q[g+5]
            //   y[g+3] = q[g+3] - q[g+4]
            #pragma unroll
            for (int k = 0; k < 4; k++) {
                const int g = 2 + 4 * k;     // qe index of group base
                v[4*k+0] = qe[g-2];
                v[4*k+1] = qe[g-1] - qe[g]   + qe[g+1];
                v[4*k+2] = qe[g+2] - qe[g+4] + qe[g+5];
                v[4*k+3] = qe[g+3] - qe[g+4];
            }
        } else {
            // MJ in registers: y = [x0-x2+x3, x1-x2, x0, x1-x2+x3]
            #pragma unroll
            for (int k = 0; k < 4; k++) {
                const float x0 = clipq(v[4*k+0], r);
                const float x1 = clipq(v[4*k+1], r);
                const float x2 = clipq(v[4*k+2], r);
                const float x3 = clipq(v[4*k+3], r);
                const float y1 = x1 - x2;
                v[4*k+0] = x0 - x2 + x3;
                v[4*k+1] = y1;
                v[4*k+2] = x0;
                v[4*k+3] = y1 + x3;
            }
        }

        // ---- dequantize (exact RN multiply, small-integer * qs) ----
        #pragma unroll
        for (int i = 0; i < 16; i++) v[i] = __fmul_rn(v[i], qs);
    }

    // ---- epilogue: out = v*scale + bias (separate RN mul, RN add) ----
    float4* __restrict__ o4 = (float4*)(out + rowbase) + t * 4;
    const float4* __restrict__ sc4 = (const float4*)scale + t * 4;
    const float4* __restrict__ bi4 = (const float4*)bias  + t * 4;
    #pragma unroll
    for (int c = 0; c < 4; c++) {
        const float4 s = __ldg(sc4 + c);
        const float4 b = __ldg(bi4 + c);
        float4 rr;
        rr.x = __fadd_rn(__fmul_rn(v[4*c+0], s.x), b.x);
        rr.y = __fadd_rn(__fmul_rn(v[4*c+1], s.y), b.y);
        rr.z = __fadd_rn(__fmul_rn(v[4*c+2], s.z), b.z);
        rr.w = __fadd_rn(__fmul_rn(v[4*c+3], s.w), b.w);
        o4[c] = rr;
    }
}

extern "C" void kernel_launch(void* const* d_in, const int* in_sizes, int n_in,
                              void* d_out, int out_size) {
    const float* x     = (const float*)d_in[0];
    const float* scale = (const float*)d_in[1];
    const float* bias  = (const float*)d_in[2];
    float* out         = (float*)d_out;
    const int rows = in_sizes[0] / DIM;   // 16384
    twist_kernel<<<rows, THREADS>>>(x, scale, bias, out);
}